// round 4
// baseline (speedup 1.0000x reference)
#include <cuda_runtime.h>

#define N_NODES 100000
#define N_EDGES 1600000
#define D 64
#define N_LAYERS 5
#define N_GRAPHS 256
#define N_RS (N_NODES + 1)
#define SCAN_B 1024
#define NB ((N_RS + SCAN_B - 1) / SCAN_B)   // 98

// ---------------- device scratch (static: no allocation at runtime) --------
__device__ float g_bufA[N_NODES * D];
__device__ float g_bufB[N_NODES * D];
__device__ int   g_src[N_EDGES];
__device__ int   g_dst[N_EDGES];
__device__ int   g_srcs[N_EDGES];       // src sorted by dst (CSR payload)
__device__ int   g_batch[N_NODES];
__device__ int   g_rowstart[N_RS];
__device__ int   g_cursor[N_NODES];
__device__ int   g_bsum[NB];
__device__ float g_pool[N_GRAPHS * D];
__device__ float g_cnt[N_GRAPHS];
__device__ int   g_flags[2];            // [0]=edge_index is int64, [1]=batch is int64

// ---------------- dtype detection (int64 vs int32) -------------------------
// If the buffers hold int64 values < 2^32, every odd 32-bit word is 0.
// edge_index words 1,3,...: random indices if int32 (can't all be 0).
// batch: probe odd words in [50001, 50512) — mid-buffer sorted graph ids are
// nonzero if int32, high halves (0) if int64.
__global__ void detect_kernel(const void* ep, const void* bp) {
    __shared__ int ez, bz;
    if (threadIdx.x == 0) { ez = 0; bz = 0; }
    __syncthreads();
    const int* ew = (const int*)ep;
    if (ew[2 * threadIdx.x + 1] != 0) atomicOr(&ez, 1);
    const int* bw = (const int*)bp;
    if (bw[50001 + 2 * threadIdx.x] != 0) atomicOr(&bz, 1);
    __syncthreads();
    if (threadIdx.x == 0) { g_flags[0] = ez ? 0 : 1; g_flags[1] = bz ? 0 : 1; }
}

__global__ void conv_edges_kernel(const void* p) {
    int e = blockIdx.x * blockDim.x + threadIdx.x;
    if (e >= N_EDGES) return;
    int s, d;
    if (g_flags[0]) {
        const long long* q = (const long long*)p;
        s = (int)q[e]; d = (int)q[N_EDGES + e];
    } else {
        const int* q = (const int*)p;
        s = q[e]; d = q[N_EDGES + e];
    }
    g_src[e] = s; g_dst[e] = d;
}

__global__ void conv_batch_kernel(const void* p) {
    int i = blockIdx.x * blockDim.x + threadIdx.x;
    if (i >= N_NODES) return;
    g_batch[i] = g_flags[1] ? (int)((const long long*)p)[i] : ((const int*)p)[i];
}

// ---------------- CSR build -------------------------------------------------
__global__ void zero_meta_kernel() {
    int i = blockIdx.x * blockDim.x + threadIdx.x;
    if (i < N_RS)          g_rowstart[i] = 0;
    if (i < N_GRAPHS * D)  g_pool[i] = 0.f;
    if (i < N_GRAPHS)      g_cnt[i] = 0.f;
}

__global__ void hist_kernel() {
    int e = blockIdx.x * blockDim.x + threadIdx.x;
    if (e < N_EDGES) atomicAdd(&g_rowstart[g_dst[e] + 1], 1);
}

__global__ __launch_bounds__(SCAN_B) void scan1_kernel() {
    __shared__ int sm[SCAN_B];
    int i = blockIdx.x * SCAN_B + threadIdx.x;
    sm[threadIdx.x] = (i < N_RS) ? g_rowstart[i] : 0;
    __syncthreads();
    for (int off = 1; off < SCAN_B; off <<= 1) {
        int t = 0;
        if ((int)threadIdx.x >= off) t = sm[threadIdx.x - off];
        __syncthreads();
        sm[threadIdx.x] += t;
        __syncthreads();
    }
    if (i < N_RS) g_rowstart[i] = sm[threadIdx.x];
    if (threadIdx.x == SCAN_B - 1) g_bsum[blockIdx.x] = sm[SCAN_B - 1];
}

__global__ void scan2_kernel() {
    __shared__ int s[128];
    int t = threadIdx.x;
    s[t] = (t < NB) ? g_bsum[t] : 0;
    __syncthreads();
    if (t == 0) {
        int run = 0;
        for (int i = 0; i < NB; i++) { int v = s[i]; s[i] = run; run += v; }
    }
    __syncthreads();
    if (t < NB) g_bsum[t] = s[t];
}

__global__ __launch_bounds__(SCAN_B) void scan3_kernel() {
    int i = blockIdx.x * SCAN_B + threadIdx.x;
    if (i < N_RS) g_rowstart[i] += g_bsum[blockIdx.x];
}

__global__ void cursor_kernel() {
    int i = blockIdx.x * blockDim.x + threadIdx.x;
    if (i < N_NODES) g_cursor[i] = g_rowstart[i];
}

__global__ void fill_kernel() {
    int e = blockIdx.x * blockDim.x + threadIdx.x;
    if (e >= N_EDGES) return;
    int d = g_dst[e];
    int p = atomicAdd(&g_cursor[d], 1);
    g_srcs[p] = g_src[e];
}

// ---------------- GIN aggregation: z[i] = h[i] + sum_{e in CSR(i)} h[src[e]]
__global__ __launch_bounds__(256) void agg_kernel(const float* __restrict__ h,
                                                  float* __restrict__ z) {
    int node = blockIdx.x * 4 + (threadIdx.x >> 6);
    int c = threadIdx.x & 63;
    if (node >= N_NODES) return;
    int s = g_rowstart[node];
    int e = g_rowstart[node + 1];
    float acc = h[node * 64 + c];
    for (int i = s; i < e; i++) {
        int sr = g_srcs[i];
        acc += __ldg(&h[sr * 64 + c]);
    }
    z[node * 64 + c] = acc;
}

// ---------------- fused MLP: out = relu(z@W1 + b1) @ W2 + b2 ---------------
__global__ __launch_bounds__(256) void mlp_kernel(
    const float* __restrict__ z, float* __restrict__ out,
    const float* __restrict__ W1, const float* __restrict__ b1,
    const float* __restrict__ W2, const float* __restrict__ b2) {
    __shared__ float sZ[64 * 64];   // [r][k]
    __shared__ float sW[64 * 64];   // [k][c]  (W1 then W2)
    __shared__ float sT[64 * 64];   // [r][k]
    int tid = threadIdx.x;
    int row0 = blockIdx.x * 64;
    int ty = tid >> 4, tx = tid & 15;

    // load z tile (zero-pad tail rows)
#pragma unroll
    for (int j = 0; j < 16; j++) {
        int idx = j * 256 + tid;
        int r = idx >> 6;
        sZ[idx] = (row0 + r < N_NODES) ? z[row0 * 64 + idx] : 0.f;
    }
#pragma unroll
    for (int j = 0; j < 4; j++) {
        int idx = (j * 256 + tid) * 4;
        *(float4*)(sW + idx) = *(const float4*)(W1 + idx);
    }
    __syncthreads();

    float a[4][4];
#pragma unroll
    for (int i = 0; i < 4; i++)
#pragma unroll
        for (int j = 0; j < 4; j++) a[i][j] = 0.f;

#pragma unroll 8
    for (int k = 0; k < 64; k++) {
        float4 w = *(float4*)(sW + (k << 6) + (tx << 2));
        float z0 = sZ[((ty << 2) + 0) * 64 + k];
        float z1 = sZ[((ty << 2) + 1) * 64 + k];
        float z2 = sZ[((ty << 2) + 2) * 64 + k];
        float z3 = sZ[((ty << 2) + 3) * 64 + k];
        a[0][0] += z0 * w.x; a[0][1] += z0 * w.y; a[0][2] += z0 * w.z; a[0][3] += z0 * w.w;
        a[1][0] += z1 * w.x; a[1][1] += z1 * w.y; a[1][2] += z1 * w.z; a[1][3] += z1 * w.w;
        a[2][0] += z2 * w.x; a[2][1] += z2 * w.y; a[2][2] += z2 * w.z; a[2][3] += z2 * w.w;
        a[3][0] += z3 * w.x; a[3][1] += z3 * w.y; a[3][2] += z3 * w.z; a[3][3] += z3 * w.w;
    }
    {
        float4 bv = *(const float4*)(b1 + (tx << 2));
#pragma unroll
        for (int i = 0; i < 4; i++) {
            float4 v;
            v.x = fmaxf(a[i][0] + bv.x, 0.f);
            v.y = fmaxf(a[i][1] + bv.y, 0.f);
            v.z = fmaxf(a[i][2] + bv.z, 0.f);
            v.w = fmaxf(a[i][3] + bv.w, 0.f);
            *(float4*)(sT + ((ty << 2) + i) * 64 + (tx << 2)) = v;
        }
    }
    __syncthreads();   // everyone done reading W1 and writing sT
#pragma unroll
    for (int j = 0; j < 4; j++) {
        int idx = (j * 256 + tid) * 4;
        *(float4*)(sW + idx) = *(const float4*)(W2 + idx);
    }
    __syncthreads();

#pragma unroll
    for (int i = 0; i < 4; i++)
#pragma unroll
        for (int j = 0; j < 4; j++) a[i][j] = 0.f;

#pragma unroll 8
    for (int k = 0; k < 64; k++) {
        float4 w = *(float4*)(sW + (k << 6) + (tx << 2));
        float t0 = sT[((ty << 2) + 0) * 64 + k];
        float t1 = sT[((ty << 2) + 1) * 64 + k];
        float t2 = sT[((ty << 2) + 2) * 64 + k];
        float t3 = sT[((ty << 2) + 3) * 64 + k];
        a[0][0] += t0 * w.x; a[0][1] += t0 * w.y; a[0][2] += t0 * w.z; a[0][3] += t0 * w.w;
        a[1][0] += t1 * w.x; a[1][1] += t1 * w.y; a[1][2] += t1 * w.z; a[1][3] += t1 * w.w;
        a[2][0] += t2 * w.x; a[2][1] += t2 * w.y; a[2][2] += t2 * w.z; a[2][3] += t2 * w.w;
        a[3][0] += t3 * w.x; a[3][1] += t3 * w.y; a[3][2] += t3 * w.z; a[3][3] += t3 * w.w;
    }
    {
        float4 bv = *(const float4*)(b2 + (tx << 2));
#pragma unroll
        for (int i = 0; i < 4; i++) {
            int r = row0 + (ty << 2) + i;
            if (r < N_NODES) {
                float4 v;
                v.x = a[i][0] + bv.x;
                v.y = a[i][1] + bv.y;
                v.z = a[i][2] + bv.z;
                v.w = a[i][3] + bv.w;
                *(float4*)(out + r * 64 + (tx << 2)) = v;
            }
        }
    }
}

// ---------------- mean pool (batch is sorted -> run-length compress atomics)
__global__ __launch_bounds__(256) void pool_kernel(const float* __restrict__ h) {
    const int NPG = 8;
    int grp = blockIdx.x * 4 + (threadIdx.x >> 6);
    int c = threadIdx.x & 63;
    int i0 = grp * NPG;
    if (i0 >= N_NODES) return;
    float acc = 0.f; int cur = -1; int run = 0;
    for (int j = 0; j < NPG; j++) {
        int i = i0 + j;
        if (i >= N_NODES) break;
        int b = g_batch[i];
        if (b != cur) {
            if (cur >= 0) {
                atomicAdd(&g_pool[cur * 64 + c], acc);
                if (c == 0) atomicAdd(&g_cnt[cur], (float)run);
            }
            acc = 0.f; cur = b; run = 0;
        }
        acc += h[i * 64 + c];
        run++;
    }
    if (cur >= 0) {
        atomicAdd(&g_pool[cur * 64 + c], acc);
        if (c == 0) atomicAdd(&g_cnt[cur], (float)run);
    }
}

// ---------------- readout MLP ----------------------------------------------
__global__ __launch_bounds__(64) void readout_kernel(
    const float* __restrict__ mW1, const float* __restrict__ mb1,
    const float* __restrict__ mW2, const float* __restrict__ mb2,
    float* __restrict__ out) {
    __shared__ float p[64], t[64];
    int g = blockIdx.x, c = threadIdx.x;
    float cnt = g_cnt[g];
    if (cnt < 1.f) cnt = 1.f;
    p[c] = g_pool[g * 64 + c] / cnt;
    __syncthreads();
    float a = mb1[c];
#pragma unroll 8
    for (int k = 0; k < 64; k++) a += p[k] * mW1[k * 64 + c];
    t[c] = a > 0.f ? a : 0.f;
    __syncthreads();
    float o = mb2[c];
#pragma unroll 8
    for (int k = 0; k < 64; k++) o += t[k] * mW2[k * 64 + c];
    out[g * 64 + c] = o;
}

// ---------------- launch ----------------------------------------------------
extern "C" void kernel_launch(void* const* d_in, const int* in_sizes, int n_in,
                              void* d_out, int out_size) {
    const float* x   = (const float*)d_in[0];
    const void*  ei  = d_in[1];
    const void*  ba  = d_in[2];
    const float* Ws1 = (const float*)d_in[3];
    const float* bs1 = (const float*)d_in[4];
    const float* Ws2 = (const float*)d_in[5];
    const float* bs2 = (const float*)d_in[6];
    const float* mW1 = (const float*)d_in[7];
    const float* mb1 = (const float*)d_in[8];
    const float* mW2 = (const float*)d_in[9];
    const float* mb2 = (const float*)d_in[10];
    float* out = (float*)d_out;

    float *bufA, *bufB;
    cudaGetSymbolAddress((void**)&bufA, g_bufA);
    cudaGetSymbolAddress((void**)&bufB, g_bufB);

    const int EG = (N_EDGES + 255) / 256;   // 6250
    const int NG = (N_NODES + 255) / 256;   // 391

    detect_kernel<<<1, 256>>>(ei, ba);
    conv_edges_kernel<<<EG, 256>>>(ei);
    conv_batch_kernel<<<NG, 256>>>(ba);
    zero_meta_kernel<<<(N_RS + 255) / 256, 256>>>();
    hist_kernel<<<EG, 256>>>();
    scan1_kernel<<<NB, SCAN_B>>>();
    scan2_kernel<<<1, 128>>>();
    scan3_kernel<<<NB, SCAN_B>>>();
    cursor_kernel<<<NG, 256>>>();
    fill_kernel<<<EG, 256>>>();

    const float* h = x;
    for (int l = 0; l < N_LAYERS; l++) {
        agg_kernel<<<(N_NODES + 3) / 4, 256>>>(h, bufB);
        mlp_kernel<<<(N_NODES + 63) / 64, 256>>>(bufB, bufA,
                                                 Ws1 + l * D * D, bs1 + l * D,
                                                 Ws2 + l * D * D, bs2 + l * D);
        h = bufA;
    }
    pool_kernel<<<(N_NODES / 8 + 3) / 4, 256>>>(h);
    readout_kernel<<<N_GRAPHS, 64>>>(mW1, mb1, mW2, mb2, out);
}